// round 1
// baseline (speedup 1.0000x reference)
#include <cuda_runtime.h>
#include <cstdint>
#include <math.h>

#define TOKENS 256
#define HID    1024
#define INTER  768
#define NEXP   32
#define TOPK   6
#define NGRP   8
#define TOPG   4

#define BM   64
#define BK   32
#define BKP  36
#define NK1  (HID/BK)    // 32
#define NK2  (INTER/BK)  // 24

// ---------------- scratch (device globals; no allocation) ----------------
__device__ int   g_cnt[NEXP];
__device__ int   g_tok[NEXP*TOKENS];
__device__ float g_wgt[NEXP*TOKENS];
__device__ float g_act[(size_t)NEXP*TOKENS*INTER];   // ~25 MB

// ---------------- helpers ----------------
__device__ __forceinline__ uint32_t f2tf(float x){
    uint32_t u; asm("cvt.rna.tf32.f32 %0, %1;" : "=r"(u) : "f"(x)); return u;
}
__device__ __forceinline__ void mma8(float* d, const uint32_t* a, const uint32_t* b){
    asm volatile(
      "mma.sync.aligned.m16n8k8.row.col.f32.tf32.tf32.f32 "
      "{%0,%1,%2,%3}, {%4,%5,%6,%7}, {%8,%9}, {%0,%1,%2,%3};\n"
      : "+f"(d[0]), "+f"(d[1]), "+f"(d[2]), "+f"(d[3])
      : "r"(a[0]), "r"(a[1]), "r"(a[2]), "r"(a[3]), "r"(b[0]), "r"(b[1]));
}

// ---------------- routing: biased grouped top-k ----------------
__global__ void routing_kernel(const float* __restrict__ logits,
                               const float* __restrict__ bias){
    __shared__ float sb[NEXP];
    const int t = threadIdx.x;
    if (t < NEXP){ g_cnt[t] = 0; sb[t] = bias[t]; }
    __syncthreads();

    float s[NEXP], sc[NEXP];
    #pragma unroll
    for (int e=0;e<NEXP;e++){
        float x = logits[t*NEXP + e];
        float sg = 1.0f/(1.0f + expf(-x));
        s[e] = sg;
        sc[e] = sg + sb[e];
    }
    // per-group top-2 sum of biased scores
    float gsv[NGRP];
    #pragma unroll
    for (int g=0; g<NGRP; g++){
        float m1 = -3e38f, m2 = -3e38f;
        #pragma unroll
        for (int j=0;j<4;j++){
            float v = sc[g*4+j];
            if (v > m1){ m2 = m1; m1 = v; }
            else if (v > m2){ m2 = v; }
        }
        gsv[g] = m1 + m2;
    }
    // top-4 groups (ties -> lowest index, matching lax.top_k)
    bool gsel[NGRP];
    #pragma unroll
    for (int g=0; g<NGRP; g++) gsel[g]=false;
    for (int it=0; it<TOPG; it++){
        int best=0; float bv=-3e38f;
        #pragma unroll
        for (int g=0; g<NGRP; g++)
            if (!gsel[g] && gsv[g] > bv){ bv=gsv[g]; best=g; }
        gsel[best]=true;
    }
    // masked top-6 experts by biased score
    float ms[NEXP];
    #pragma unroll
    for (int e=0;e<NEXP;e++) ms[e] = gsel[e>>2] ? sc[e] : -3e38f;

    int ids[TOPK]; float ws[TOPK]; float wsum=0.f;
    for (int k=0;k<TOPK;k++){
        int best=0; float bv=-3e38f;
        #pragma unroll
        for (int e=0;e<NEXP;e++)
            if (ms[e] > bv){ bv=ms[e]; best=e; }
        ms[best] = -3.2e38f;
        ids[k]=best; ws[k]=s[best]; wsum += s[best];
    }
    float inv = 1.0f/wsum;
    for (int k=0;k<TOPK;k++){
        int eidx = ids[k];
        int pos = atomicAdd(&g_cnt[eidx], 1);
        g_tok[eidx*TOKENS + pos] = t;
        g_wgt[eidx*TOKENS + pos] = ws[k]*inv;
    }
}

// ---------------- GEMM1: act = silu(X W13g^T) * (X W13u^T), gathered per expert ----------------
__global__ void __launch_bounds__(256)
gemm1_kernel(const float* __restrict__ hidden, const float* __restrict__ w13){
    const int e   = blockIdx.z;
    const int cnt = g_cnt[e];
    const int m0  = blockIdx.y * BM;
    if (m0 >= cnt) return;
    const int i0  = blockIdx.x * 64;

    extern __shared__ uint32_t sm[];
    uint32_t* smA = sm;               // [2][BM][BKP]
    uint32_t* smB = sm + 2*BM*BKP;    // [2][128][BKP]  (64 gate rows + 64 up rows)

    const int tid  = threadIdx.x;
    const int lane = tid & 31;
    const int warp = tid >> 5;
    const int wm = warp >> 1;     // 0..3 : 16-row slice
    const int wn = warp & 1;      // 0..1 : 32-i slice
    const int gq = lane >> 2;
    const int tg = lane & 3;

    // A: 64x32 floats -> 512 float4 -> 2 per thread (gathered token rows)
    const float* aptr[2];
    #pragma unroll
    for (int v=0; v<2; v++){
        int idx = tid*2 + v;
        int r = idx >> 3;
        int c = (idx & 7) * 4;
        int p = m0 + r;
        if (p < cnt){
            int tk = g_tok[e*TOKENS + p];
            aptr[v] = hidden + (size_t)tk*HID + c;
        } else aptr[v] = nullptr;
    }
    // B: 128x32 floats -> 1024 float4 -> 4 per thread (gate rows then up rows)
    const float* bptr[4];
    #pragma unroll
    for (int v=0; v<4; v++){
        int idx = tid*4 + v;
        int j = idx >> 3;
        int c = (idx & 7)*4;
        int row = (j < 64) ? (i0 + j) : (INTER + i0 + j - 64);
        bptr[v] = w13 + ((size_t)e*(2*INTER) + row)*HID + c;
    }

    float ra[8], rb[16];
    auto ldg = [&](int kc){
        const int k0 = kc*BK;
        #pragma unroll
        for (int v=0; v<2; v++){
            float4 f = aptr[v] ? *(const float4*)(aptr[v]+k0)
                               : make_float4(0.f,0.f,0.f,0.f);
            ra[4*v]=f.x; ra[4*v+1]=f.y; ra[4*v+2]=f.z; ra[4*v+3]=f.w;
        }
        #pragma unroll
        for (int v=0; v<4; v++){
            float4 f = *(const float4*)(bptr[v]+k0);
            rb[4*v]=f.x; rb[4*v+1]=f.y; rb[4*v+2]=f.z; rb[4*v+3]=f.w;
        }
    };
    auto sts = [&](int buf){
        #pragma unroll
        for (int v=0; v<2; v++){
            int idx = tid*2+v; int r = idx>>3; int c = (idx&7)*4;
            uint4 u = make_uint4(f2tf(ra[4*v]),f2tf(ra[4*v+1]),f2tf(ra[4*v+2]),f2tf(ra[4*v+3]));
            *(uint4*)&smA[((buf*BM)+r)*BKP + c] = u;
        }
        #pragma unroll
        for (int v=0; v<4; v++){
            int idx = tid*4+v; int r = idx>>3; int c = (idx&7)*4;
            uint4 u = make_uint4(f2tf(rb[4*v]),f2tf(rb[4*v+1]),f2tf(rb[4*v+2]),f2tf(rb[4*v+3]));
            *(uint4*)&smB[((buf*128)+r)*BKP + c] = u;
        }
    };

    float accG[4][4], accU[4][4];
    #pragma unroll
    for (int i=0;i<4;i++)
        #pragma unroll
        for(int j=0;j<4;j++){ accG[i][j]=0.f; accU[i][j]=0.f; }

    ldg(0); sts(0); __syncthreads();
    ldg(1);

    const int aRow  = wm*16 + gq;
    const int bRow0 = wn*32 + gq;

    for (int kc=0; kc<NK1; kc++){
        const int buf = kc & 1;
        const uint32_t* A0 = &smA[(buf*BM)*BKP];
        const uint32_t* B0 = &smB[(buf*128)*BKP];
        #pragma unroll
        for (int kk=0; kk<4; kk++){
            const int k = kk*8;
            uint32_t a[4];
            a[0] = A0[(aRow  )*BKP + k + tg];
            a[1] = A0[(aRow+8)*BKP + k + tg];
            a[2] = A0[(aRow  )*BKP + k + tg + 4];
            a[3] = A0[(aRow+8)*BKP + k + tg + 4];
            #pragma unroll
            for (int nt=0; nt<4; nt++){
                const int n = bRow0 + nt*8;
                uint32_t b[2];
                b[0] = B0[(n)*BKP + k + tg];
                b[1] = B0[(n)*BKP + k + tg + 4];
                mma8(accG[nt], a, b);
                b[0] = B0[(n+64)*BKP + k + tg];
                b[1] = B0[(n+64)*BKP + k + tg + 4];
                mma8(accU[nt], a, b);
            }
        }
        if (kc+1 < NK1){
            sts((kc+1)&1);
            __syncthreads();
            if (kc+2 < NK1) ldg(kc+2);
        }
    }

    // fused SiLU(gate)*up epilogue -> act
    const size_t actBase = (size_t)e * TOKENS * INTER;
    #pragma unroll
    for (int h=0; h<2; h++){
        int r = m0 + wm*16 + gq + h*8;
        if (r < cnt){
            float* arow = g_act + actBase + (size_t)r*INTER + i0 + wn*32;
            #pragma unroll
            for (int nt=0; nt<4; nt++){
                #pragma unroll
                for (int c2=0; c2<2; c2++){
                    float gv = accG[nt][h*2+c2];
                    float uv = accU[nt][h*2+c2];
                    arow[nt*8 + 2*tg + c2] = gv / (1.0f + expf(-gv)) * uv;
                }
            }
        }
    }
}

// ---------------- GEMM2: y = act W2^T, scatter w*y into out ----------------
__global__ void __launch_bounds__(256)
gemm2_kernel(const float* __restrict__ w2, float* __restrict__ out){
    const int e   = blockIdx.z;
    const int cnt = g_cnt[e];
    const int m0  = blockIdx.y * BM;
    if (m0 >= cnt) return;
    const int h0  = blockIdx.x * 64;

    extern __shared__ uint32_t sm[];
    uint32_t* smA = sm;               // [2][64][BKP]
    uint32_t* smB = sm + 2*BM*BKP;    // [2][64][BKP]

    const int tid  = threadIdx.x;
    const int lane = tid & 31;
    const int warp = tid >> 5;
    const int wm = warp >> 1;
    const int wn = warp & 1;
    const int gq = lane >> 2;
    const int tg = lane & 3;

    const float* aptr[2];
    #pragma unroll
    for (int v=0; v<2; v++){
        int idx = tid*2+v; int r = idx>>3; int c = (idx&7)*4;
        int p = m0 + r;
        aptr[v] = (p<cnt) ? g_act + ((size_t)e*TOKENS + p)*INTER + c : nullptr;
    }
    const float* bptr[2];
    #pragma unroll
    for (int v=0; v<2; v++){
        int idx = tid*2+v; int j = idx>>3; int c = (idx&7)*4;
        bptr[v] = w2 + ((size_t)e*HID + h0 + j)*INTER + c;
    }

    float ra[8], rb[8];
    auto ldg = [&](int kc){
        const int k0 = kc*BK;
        #pragma unroll
        for (int v=0; v<2; v++){
            float4 f = aptr[v] ? *(const float4*)(aptr[v]+k0)
                               : make_float4(0.f,0.f,0.f,0.f);
            ra[4*v]=f.x; ra[4*v+1]=f.y; ra[4*v+2]=f.z; ra[4*v+3]=f.w;
        }
        #pragma unroll
        for (int v=0; v<2; v++){
            float4 f = *(const float4*)(bptr[v]+k0);
            rb[4*v]=f.x; rb[4*v+1]=f.y; rb[4*v+2]=f.z; rb[4*v+3]=f.w;
        }
    };
    auto sts = [&](int buf){
        #pragma unroll
        for (int v=0; v<2; v++){
            int idx = tid*2+v; int r = idx>>3; int c = (idx&7)*4;
            uint4 u = make_uint4(f2tf(ra[4*v]),f2tf(ra[4*v+1]),f2tf(ra[4*v+2]),f2tf(ra[4*v+3]));
            *(uint4*)&smA[((buf*BM)+r)*BKP + c] = u;
        }
        #pragma unroll
        for (int v=0; v<2; v++){
            int idx = tid*2+v; int r = idx>>3; int c = (idx&7)*4;
            uint4 u = make_uint4(f2tf(rb[4*v]),f2tf(rb[4*v+1]),f2tf(rb[4*v+2]),f2tf(rb[4*v+3]));
            *(uint4*)&smB[((buf*64)+r)*BKP + c] = u;
        }
    };

    float acc[4][4];
    #pragma unroll
    for (int i=0;i<4;i++)
        #pragma unroll
        for(int j=0;j<4;j++) acc[i][j]=0.f;

    ldg(0); sts(0); __syncthreads();
    ldg(1);

    const int aRow  = wm*16 + gq;
    const int bRow0 = wn*32 + gq;

    for (int kc=0; kc<NK2; kc++){
        const int buf = kc & 1;
        const uint32_t* A0 = &smA[(buf*BM)*BKP];
        const uint32_t* B0 = &smB[(buf*64)*BKP];
        #pragma unroll
        for (int kk=0; kk<4; kk++){
            const int k = kk*8;
            uint32_t a[4];
            a[0] = A0[(aRow  )*BKP + k + tg];
            a[1] = A0[(aRow+8)*BKP + k + tg];
            a[2] = A0[(aRow  )*BKP + k + tg + 4];
            a[3] = A0[(aRow+8)*BKP + k + tg + 4];
            #pragma unroll
            for (int nt=0; nt<4; nt++){
                const int n = bRow0 + nt*8;
                uint32_t b[2];
                b[0] = B0[(n)*BKP + k + tg];
                b[1] = B0[(n)*BKP + k + tg + 4];
                mma8(acc[nt], a, b);
            }
        }
        if (kc+1 < NK2){
            sts((kc+1)&1);
            __syncthreads();
            if (kc+2 < NK2) ldg(kc+2);
        }
    }

    // scatter-accumulate: out[t, h] += w * y
    #pragma unroll
    for (int h=0; h<2; h++){
        int r = m0 + wm*16 + gq + h*8;
        if (r < cnt){
            int   tk = g_tok[e*TOKENS + r];
            float w  = g_wgt[e*TOKENS + r];
            float* orow = out + (size_t)tk*HID + h0 + wn*32;
            #pragma unroll
            for (int nt=0; nt<4; nt++){
                atomicAdd(&orow[nt*8 + 2*tg    ], w*acc[nt][h*2+0]);
                atomicAdd(&orow[nt*8 + 2*tg + 1], w*acc[nt][h*2+1]);
            }
        }
    }
}

// ---------------- launch ----------------
extern "C" void kernel_launch(void* const* d_in, const int* in_sizes, int n_in,
                              void* d_out, int out_size){
    const float* hidden = (const float*)d_in[0];
    const float* logits = (const float*)d_in[1];
    const float* bias   = (const float*)d_in[2];
    const float* w13    = (const float*)d_in[3];
    const float* w2     = (const float*)d_in[4];
    float* out = (float*)d_out;

    const int SMEM1 = 2*(BM+128)*BKP*4;  // 55296 B
    const int SMEM2 = 2*(BM+ 64)*BKP*4;  // 36864 B
    cudaFuncSetAttribute(gemm1_kernel, cudaFuncAttributeMaxDynamicSharedMemorySize, SMEM1);
    cudaFuncSetAttribute(gemm2_kernel, cudaFuncAttributeMaxDynamicSharedMemorySize, SMEM2);

    cudaMemsetAsync(d_out, 0, (size_t)TOKENS*HID*sizeof(float));
    routing_kernel<<<1, TOKENS>>>(logits, bias);
    gemm1_kernel<<<dim3(INTER/64, TOKENS/BM, NEXP), 256, SMEM1>>>(hidden, w13);
    gemm2_kernel<<<dim3(HID/64,  TOKENS/BM, NEXP), 256, SMEM2>>>(w2, out);
}

// round 5
// speedup vs baseline: 1.4919x; 1.4919x over previous
#include <cuda_runtime.h>
#include <cuda_fp16.h>
#include <cstdint>
#include <math.h>

#define TOKENS 256
#define HID    1024
#define INTER  768
#define NEXP   32
#define NGRP   8
#define TOPG   4
#define TOPK   6
#define BK     32
#define NK1    (HID/BK)    // 32
#define NK2    (INTER/BK)  // 24
#define PITCH  40          // halfs per smem row (80B: conflict-free ldmatrix)

// ---------------- scratch (device globals; no allocation) ----------------
__device__ int    g_cnt[NEXP];
__device__ int    g_tok[NEXP*TOKENS];
__device__ float  g_wgt[NEXP*TOKENS];
__device__ __half g_act[(size_t)NEXP*TOKENS*INTER];   // ~12.5 MB

// ---------------- helpers ----------------
__device__ __forceinline__ uint32_t smem_u32(const void* p){
    uint32_t a;
    asm("{ .reg .u64 t; cvta.to.shared.u64 t, %1; cvt.u32.u64 %0, t; }" : "=r"(a) : "l"(p));
    return a;
}
__device__ __forceinline__ void ldm4(uint32_t* r, uint32_t addr){
    asm volatile("ldmatrix.sync.aligned.m8n8.x4.shared.b16 {%0,%1,%2,%3}, [%4];"
        : "=r"(r[0]), "=r"(r[1]), "=r"(r[2]), "=r"(r[3]) : "r"(addr));
}
__device__ __forceinline__ void mma16(float* d, const uint32_t* a, const uint32_t* b){
    asm volatile(
      "mma.sync.aligned.m16n8k16.row.col.f32.f16.f16.f32 "
      "{%0,%1,%2,%3},{%4,%5,%6,%7},{%8,%9},{%0,%1,%2,%3};\n"
      : "+f"(d[0]), "+f"(d[1]), "+f"(d[2]), "+f"(d[3])
      : "r"(a[0]), "r"(a[1]), "r"(a[2]), "r"(a[3]), "r"(b[0]), "r"(b[1]));
}
__device__ __forceinline__ uint32_t pk(float a, float b){
    __half2 h = __floats2half2_rn(a, b);
    return *(uint32_t*)&h;
}

// ---------------- zero g_cnt (replaces symbol memset, which crashed the harness) ----
__global__ void zero_kernel(){
    if (threadIdx.x < NEXP) g_cnt[threadIdx.x] = 0;
}

// ---------------- routing: biased grouped top-k (8 blocks x 32 threads) ----------------
__global__ void routing_kernel(const float* __restrict__ logits,
                               const float* __restrict__ bias){
    const int t = blockIdx.x * 32 + threadIdx.x;

    float s[NEXP], sc[NEXP];
    #pragma unroll
    for (int e=0;e<NEXP;e++){
        float x  = logits[t*NEXP + e];
        float sg = 1.0f/(1.0f + expf(-x));
        s[e]  = sg;
        sc[e] = sg + bias[e];
    }
    float gsv[NGRP];
    #pragma unroll
    for (int g=0; g<NGRP; g++){
        float m1 = -3e38f, m2 = -3e38f;
        #pragma unroll
        for (int j=0;j<4;j++){
            float v = sc[g*4+j];
            if (v > m1){ m2 = m1; m1 = v; }
            else if (v > m2){ m2 = v; }
        }
        gsv[g] = m1 + m2;
    }
    bool gsel[NGRP];
    #pragma unroll
    for (int g=0; g<NGRP; g++) gsel[g]=false;
    for (int it=0; it<TOPG; it++){
        int best=0; float bv=-3e38f;
        #pragma unroll
        for (int g=0; g<NGRP; g++)
            if (!gsel[g] && gsv[g] > bv){ bv=gsv[g]; best=g; }
        gsel[best]=true;
    }
    float ms[NEXP];
    #pragma unroll
    for (int e=0;e<NEXP;e++) ms[e] = gsel[e>>2] ? sc[e] : -3e38f;

    int ids[TOPK]; float ws[TOPK]; float wsum=0.f;
    for (int k=0;k<TOPK;k++){
        int best=0; float bv=-3e38f;
        #pragma unroll
        for (int e=0;e<NEXP;e++)
            if (ms[e] > bv){ bv=ms[e]; best=e; }
        ms[best] = -3.2e38f;
        ids[k]=best; ws[k]=s[best]; wsum += s[best];
    }
    float inv = 1.0f/wsum;
    for (int k=0;k<TOPK;k++){
        int eidx = ids[k];
        int pos = atomicAdd(&g_cnt[eidx], 1);
        g_tok[eidx*TOKENS + pos] = t;
        g_wgt[eidx*TOKENS + pos] = ws[k]*inv;
    }
}

// ---------------- GEMM1: act = silu(X W13g^T) * (X W13u^T) ----------------
// block tile: M=64 tokens x N=64 inter (gate+up => 128 B-rows), BK=32
// smem stage: A 64xPITCH halfs (5120B) + B 128xPITCH halfs (10240B) = 15360B, x2
#define G1_STAGE 15360
#define G1_BOFF  5120

__global__ void __launch_bounds__(256)
gemm1_kernel(const float* __restrict__ hidden, const float* __restrict__ w13){
    const int e   = blockIdx.z;
    const int cnt = g_cnt[e];
    const int m0  = blockIdx.y * 64;
    if (m0 >= cnt) return;
    const int i0  = blockIdx.x * 64;

    extern __shared__ __align__(16) char smem[];
    const uint32_t sbase = smem_u32(smem);
    __shared__ int stok[64];

    const int tid  = threadIdx.x;
    const int warp = tid >> 5;
    const int lane = tid & 31;
    const int wm = warp >> 1;      // 0..3
    const int wn = warp & 1;       // 0..1

    if (tid < 64) stok[tid] = (m0 + tid < cnt) ? g_tok[e*TOKENS + m0 + tid] : -1;
    __syncthreads();

    // load mapping: A 64 rows x 4 cpair(8 halfs) = 256 slots (1/thread)
    //               B 128 rows x 4 cpair = 512 slots (2/thread)
    const int arow = tid >> 2, acp = tid & 3;
    const int tk = stok[arow];
    const float* ap = (tk >= 0) ? hidden + (size_t)tk*HID + acp*8 : nullptr;
    const uint32_t sAoff = (uint32_t)(arow*PITCH + acp*8)*2;

    const float* bp[2]; uint32_t sBoff[2];
    #pragma unroll
    for (int v=0; v<2; v++){
        int idx = v*256 + tid;
        int brow = idx >> 2, bcp = idx & 3;
        int wrow = (brow < 64) ? (i0 + brow) : (INTER + i0 + brow - 64);
        bp[v] = w13 + ((size_t)e*(2*INTER) + wrow)*HID + bcp*8;
        sBoff[v] = (uint32_t)(brow*PITCH + bcp*8)*2;
    }

    uint4 ua, ub[2];
    auto ldg = [&](int kc){
        const int k0 = kc*BK;
        if (ap){
            float4 f0 = *(const float4*)(ap + k0);
            float4 f1 = *(const float4*)(ap + k0 + 4);
            ua = make_uint4(pk(f0.x,f0.y), pk(f0.z,f0.w), pk(f1.x,f1.y), pk(f1.z,f1.w));
        } else ua = make_uint4(0,0,0,0);
        #pragma unroll
        for (int v=0; v<2; v++){
            float4 f0 = *(const float4*)(bp[v] + k0);
            float4 f1 = *(const float4*)(bp[v] + k0 + 4);
            ub[v] = make_uint4(pk(f0.x,f0.y), pk(f0.z,f0.w), pk(f1.x,f1.y), pk(f1.z,f1.w));
        }
    };
    auto sts = [&](int s){
        *(uint4*)(smem + s*G1_STAGE + sAoff) = ua;
        #pragma unroll
        for (int v=0; v<2; v++)
            *(uint4*)(smem + s*G1_STAGE + G1_BOFF + sBoff[v]) = ub[v];
    };

    // ldmatrix lane addressing
    const int t8 = lane >> 3, rr = lane & 7;
    const uint32_t aOff = (uint32_t)(((wm*16 + (t8&1)*8 + rr)*PITCH + (t8>>1)*8))*2;
    const uint32_t bRowN = (uint32_t)((t8>>1)*8 + rr);
    const uint32_t bKB   = (uint32_t)((t8&1)*8)*2;
    uint32_t bOffG[2], bOffU[2];
    #pragma unroll
    for (int nb=0; nb<2; nb++){
        bOffG[nb] = (uint32_t)((wn*32 + nb*16 + bRowN)*PITCH)*2 + bKB;
        bOffU[nb] = bOffG[nb] + (uint32_t)(64*PITCH)*2;
    }

    float accG[4][4], accU[4][4];
    #pragma unroll
    for (int i=0;i<4;i++)
        #pragma unroll
        for (int j=0;j<4;j++){ accG[i][j]=0.f; accU[i][j]=0.f; }

    ldg(0); sts(0); __syncthreads();
    ldg(1);

    for (int kc=0; kc<NK1; kc++){
        const int s = kc & 1;
        const uint32_t sA = sbase + s*G1_STAGE;
        const uint32_t sB = sA + G1_BOFF;
        #pragma unroll
        for (int kk=0; kk<2; kk++){
            uint32_t a[4], b0[4], b1[4], u0[4], u1[4];
            ldm4(a,  sA + aOff + kk*32);
            ldm4(b0, sB + bOffG[0] + kk*32);
            ldm4(b1, sB + bOffG[1] + kk*32);
            ldm4(u0, sB + bOffU[0] + kk*32);
            ldm4(u1, sB + bOffU[1] + kk*32);
            mma16(accG[0], a, b0);   mma16(accG[1], a, b0+2);
            mma16(accG[2], a, b1);   mma16(accG[3], a, b1+2);
            mma16(accU[0], a, u0);   mma16(accU[1], a, u0+2);
            mma16(accU[2], a, u1);   mma16(accU[3], a, u1+2);
        }
        if (kc+1 < NK1){
            sts((kc+1)&1);
            __syncthreads();
            if (kc+2 < NK1) ldg(kc+2);
        }
    }

    // epilogue: silu(gate)*up -> g_act (fp16)
    const int gq = lane >> 2, tg = lane & 3;
    #pragma unroll
    for (int h=0; h<2; h++){
        int r = wm*16 + gq + h*8;
        if (m0 + r < cnt){
            __half* arow_p = g_act + ((size_t)e*TOKENS + m0 + r)*INTER + i0 + wn*32;
            #pragma unroll
            for (int nt=0; nt<4; nt++){
                float g0 = accG[nt][h*2+0], g1 = accG[nt][h*2+1];
                float u0 = accU[nt][h*2+0], u1 = accU[nt][h*2+1];
                float v0 = g0/(1.0f+expf(-g0))*u0;
                float v1 = g1/(1.0f+expf(-g1))*u1;
                __half2 hv = __floats2half2_rn(v0, v1);
                *(__half2*)(arow_p + nt*8 + 2*tg) = hv;
            }
        }
    }
}

// ---------------- GEMM2: y = act W2^T, scatter w*y into out ----------------
// block tile: M=64 tokens x N=64 hidden, BK=32
// smem stage: A 64xPITCH (5120B) + B 64xPITCH (5120B) = 10240B, x2
#define G2_STAGE 10240
#define G2_BOFF  5120

__global__ void __launch_bounds__(256)
gemm2_kernel(const float* __restrict__ w2, float* __restrict__ out){
    const int e   = blockIdx.z;
    const int cnt = g_cnt[e];
    const int m0  = blockIdx.y * 64;
    if (m0 >= cnt) return;
    const int h0  = blockIdx.x * 64;

    extern __shared__ __align__(16) char smem[];
    const uint32_t sbase = smem_u32(smem);
    __shared__ int   stok[64];
    __shared__ float swgt[64];

    const int tid  = threadIdx.x;
    const int warp = tid >> 5;
    const int lane = tid & 31;
    const int wm = warp >> 1;
    const int wn = warp & 1;

    if (tid < 64){
        bool ok = (m0 + tid < cnt);
        stok[tid] = ok ? g_tok[e*TOKENS + m0 + tid] : 0;
        swgt[tid] = ok ? g_wgt[e*TOKENS + m0 + tid] : 0.f;
    }
    __syncthreads();

    const int arow = tid >> 2, acp = tid & 3;
    const __half* ap = (m0 + arow < cnt)
        ? g_act + ((size_t)e*TOKENS + m0 + arow)*INTER + acp*8 : nullptr;
    const uint32_t sAoff = (uint32_t)(arow*PITCH + acp*8)*2;

    const int brow = tid >> 2, bcp = tid & 3;
    const float* bpp = w2 + ((size_t)e*HID + h0 + brow)*INTER + bcp*8;
    const uint32_t sBoff = (uint32_t)(brow*PITCH + bcp*8)*2;

    uint4 ua, ub;
    auto ldg = [&](int kc){
        const int k0 = kc*BK;
        ua = ap ? *(const uint4*)(ap + k0) : make_uint4(0,0,0,0);
        float4 f0 = *(const float4*)(bpp + k0);
        float4 f1 = *(const float4*)(bpp + k0 + 4);
        ub = make_uint4(pk(f0.x,f0.y), pk(f0.z,f0.w), pk(f1.x,f1.y), pk(f1.z,f1.w));
    };
    auto sts = [&](int s){
        *(uint4*)(smem + s*G2_STAGE + sAoff) = ua;
        *(uint4*)(smem + s*G2_STAGE + G2_BOFF + sBoff) = ub;
    };

    const int t8 = lane >> 3, rr = lane & 7;
    const uint32_t aOff = (uint32_t)(((wm*16 + (t8&1)*8 + rr)*PITCH + (t8>>1)*8))*2;
    const uint32_t bRowN = (uint32_t)((t8>>1)*8 + rr);
    const uint32_t bKB   = (uint32_t)((t8&1)*8)*2;
    uint32_t bOff[2];
    #pragma unroll
    for (int nb=0; nb<2; nb++)
        bOff[nb] = (uint32_t)((wn*32 + nb*16 + bRowN)*PITCH)*2 + bKB;

    float acc[4][4];
    #pragma unroll
    for (int i=0;i<4;i++)
        #pragma unroll
        for (int j=0;j<4;j++) acc[i][j]=0.f;

    ldg(0); sts(0); __syncthreads();
    ldg(1);

    for (int kc=0; kc<NK2; kc++){
        const int s = kc & 1;
        const uint32_t sA = sbase + s*G2_STAGE;
        const uint32_t sB = sA + G2_BOFF;
        #pragma unroll
        for (int kk=0; kk<2; kk++){
            uint32_t a[4], b0[4], b1[4];
            ldm4(a,  sA + aOff + kk*32);
            ldm4(b0, sB + bOff[0] + kk*32);
            ldm4(b1, sB + bOff[1] + kk*32);
            mma16(acc[0], a, b0);  mma16(acc[1], a, b0+2);
            mma16(acc[2], a, b1);  mma16(acc[3], a, b1+2);
        }
        if (kc+1 < NK2){
            sts((kc+1)&1);
            __syncthreads();
            if (kc+2 < NK2) ldg(kc+2);
        }
    }

    const int gq = lane >> 2, tg = lane & 3;
    #pragma unroll
    for (int h=0; h<2; h++){
        int r = wm*16 + gq + h*8;
        if (m0 + r < cnt){
            int   tk = stok[r];
            float w  = swgt[r];
            float* orow = out + (size_t)tk*HID + h0 + wn*32;
            #pragma unroll
            for (int nt=0; nt<4; nt++){
                atomicAdd(&orow[nt*8 + 2*tg    ], w*acc[nt][h*2+0]);
                atomicAdd(&orow[nt*8 + 2*tg + 1], w*acc[nt][h*2+1]);
            }
        }
    }
}

// ---------------- launch ----------------
extern "C" void kernel_launch(void* const* d_in, const int* in_sizes, int n_in,
                              void* d_out, int out_size){
    const float* hidden = (const float*)d_in[0];
    const float* logits = (const float*)d_in[1];
    const float* bias   = (const float*)d_in[2];
    const float* w13    = (const float*)d_in[3];
    const float* w2     = (const float*)d_in[4];
    float* out = (float*)d_out;

    const int SMEM1 = 2*G1_STAGE;   // 30720
    const int SMEM2 = 2*G2_STAGE;   // 20480
    cudaFuncSetAttribute(gemm1_kernel, cudaFuncAttributeMaxDynamicSharedMemorySize, SMEM1);
    cudaFuncSetAttribute(gemm2_kernel, cudaFuncAttributeMaxDynamicSharedMemorySize, SMEM2);

    cudaMemsetAsync(d_out, 0, (size_t)TOKENS*HID*sizeof(float));
    zero_kernel<<<1, 32>>>();
    routing_kernel<<<8, 32>>>(logits, bias);
    gemm1_kernel<<<dim3(INTER/64, TOKENS/64, NEXP), 256, SMEM1>>>(hidden, w13);
    gemm2_kernel<<<dim3(HID/64,  TOKENS/64, NEXP), 256, SMEM2>>>(w2, out);
}